// round 1
// baseline (speedup 1.0000x reference)
#include <cuda_runtime.h>
#include <math.h>

#define DM   1024
#define FFN_ 4096
#define NE   8
#define TMAX 8192

// ---------------- device scratch (no allocations allowed) ----------------
__device__ int   g_counts[NE];
__device__ int   g_base[NE];
__device__ int   g_tok[NE][TMAX];
__device__ float g_gate[NE][TMAX];
__device__ float g_H[2 * TMAX][FFN_];   // grouped rows: base[e] + slot

// ---------------- small kernels ----------------
__global__ void init_kernel() {
    if (threadIdx.x < NE) g_counts[threadIdx.x] = 0;
}

__global__ void base_kernel() {
    if (threadIdx.x == 0) {
        int s = 0;
        #pragma unroll
        for (int e = 0; e < NE; e++) { g_base[e] = s; s += g_counts[e]; }
    }
}

// routing: one warp per token
__global__ void route_kernel(const float* __restrict__ x,
                             const float* __restrict__ gw,
                             const float* __restrict__ gb,
                             int T) {
    int warp = (blockIdx.x * blockDim.x + threadIdx.x) >> 5;
    int lane = threadIdx.x & 31;
    if (warp >= T) return;
    const float* xr = x + (size_t)warp * DM;

    float acc[NE];
    #pragma unroll
    for (int e = 0; e < NE; e++) acc[e] = 0.f;

    for (int d = lane; d < DM; d += 32) {
        float xv = xr[d];
        const float4* g4 = (const float4*)(gw + (size_t)d * NE);
        float4 a = g4[0], b = g4[1];
        acc[0] += xv * a.x; acc[1] += xv * a.y; acc[2] += xv * a.z; acc[3] += xv * a.w;
        acc[4] += xv * b.x; acc[5] += xv * b.y; acc[6] += xv * b.z; acc[7] += xv * b.w;
    }
    #pragma unroll
    for (int e = 0; e < NE; e++) {
        #pragma unroll
        for (int o = 16; o > 0; o >>= 1) acc[e] += __shfl_xor_sync(0xFFFFFFFFu, acc[e], o);
    }

    if (lane == 0) {
        float v[NE];
        #pragma unroll
        for (int e = 0; e < NE; e++) v[e] = acc[e] + gb[e];
        int i1 = 0;
        #pragma unroll
        for (int e = 1; e < NE; e++) if (v[e] > v[i1]) i1 = e;
        int i2 = (i1 == 0) ? 1 : 0;
        #pragma unroll
        for (int e = 0; e < NE; e++) if (e != i1 && v[e] > v[i2]) i2 = e;

        float e2 = expf(v[i2] - v[i1]);
        float s  = 1.f + e2;
        float g1 = 1.f / s;
        float g2 = e2 / s;

        int s1 = atomicAdd(&g_counts[i1], 1);
        g_tok[i1][s1] = warp; g_gate[i1][s1] = g1;
        int s2 = atomicAdd(&g_counts[i2], 1);
        g_tok[i2][s2] = warp; g_gate[i2][s2] = g2;
    }
}

__device__ __forceinline__ float gelu_exact(float v) {
    return 0.5f * v * (1.f + erff(v * 0.7071067811865476f));
}

// ---------------- GEMM1: H = gelu(X_gather @ W1[e] + b1[e]) ----------------
// tiles 128x128, BK=8, 256 threads, 8x8 per thread
__global__ __launch_bounds__(256)
void gemm1_kernel(const float* __restrict__ x,
                  const float* __restrict__ w1,
                  const float* __restrict__ b1) {
    const int e = blockIdx.z;
    const int count = g_counts[e];
    const int m0 = blockIdx.x * 128;
    if (m0 >= count) return;
    const int n0 = blockIdx.y * 128;

    __shared__ float As[8][128];
    __shared__ float Bs[8][128];

    const int tid  = threadIdx.x;
    const int arow = tid >> 1;
    const int akq  = (tid & 1) * 4;
    int tok = -1;
    if (m0 + arow < count) tok = g_tok[e][m0 + arow];
    const float* aptr = x + (size_t)((tok < 0) ? 0 : tok) * DM + akq;

    const int bk  = tid >> 5;
    const int bn4 = (tid & 31) * 4;
    const float* bptr = w1 + (size_t)e * DM * FFN_ + (size_t)bk * FFN_ + n0 + bn4;

    const int tm = (tid >> 4) * 8;
    const int tn = (tid & 15) * 8;

    float acc[8][8];
    #pragma unroll
    for (int i = 0; i < 8; i++)
        #pragma unroll
        for (int j = 0; j < 8; j++) acc[i][j] = 0.f;

    for (int k0 = 0; k0 < DM; k0 += 8) {
        float4 av = make_float4(0.f, 0.f, 0.f, 0.f);
        if (tok >= 0) av = *(const float4*)(aptr + k0);
        As[akq + 0][arow] = av.x;
        As[akq + 1][arow] = av.y;
        As[akq + 2][arow] = av.z;
        As[akq + 3][arow] = av.w;
        *(float4*)&Bs[bk][bn4] = *(const float4*)(bptr + (size_t)k0 * FFN_);
        __syncthreads();

        #pragma unroll
        for (int k = 0; k < 8; k++) {
            float4 a0 = *(float4*)&As[k][tm];
            float4 a1 = *(float4*)&As[k][tm + 4];
            float4 b0 = *(float4*)&Bs[k][tn];
            float4 b1v = *(float4*)&Bs[k][tn + 4];
            float ar[8] = {a0.x, a0.y, a0.z, a0.w, a1.x, a1.y, a1.z, a1.w};
            float br[8] = {b0.x, b0.y, b0.z, b0.w, b1v.x, b1v.y, b1v.z, b1v.w};
            #pragma unroll
            for (int i = 0; i < 8; i++)
                #pragma unroll
                for (int j = 0; j < 8; j++) acc[i][j] += ar[i] * br[j];
        }
        __syncthreads();
    }

    const int base = g_base[e];
    #pragma unroll
    for (int i = 0; i < 8; i++) {
        int m = m0 + tm + i;
        if (m < count) {
            float* hrow = &g_H[base + m][n0 + tn];
            #pragma unroll
            for (int j = 0; j < 8; j++) {
                float v = acc[i][j] + b1[(size_t)e * FFN_ + n0 + tn + j];
                hrow[j] = gelu_exact(v);
            }
        }
    }
}

// ---------------- GEMM2: out[tok] += gate * (H @ W2[e] + b2[e]) ----------------
__global__ __launch_bounds__(256)
void gemm2_kernel(const float* __restrict__ w2,
                  const float* __restrict__ b2,
                  float* __restrict__ out) {
    const int e = blockIdx.z;
    const int count = g_counts[e];
    const int m0 = blockIdx.x * 128;
    if (m0 >= count) return;
    const int n0 = blockIdx.y * 128;
    const int base = g_base[e];

    __shared__ float As[8][128];
    __shared__ float Bs[8][128];

    const int tid  = threadIdx.x;
    const int arow = tid >> 1;
    const int akq  = (tid & 1) * 4;
    const bool avalid = (m0 + arow < count);
    const float* aptr = &g_H[base + (avalid ? (m0 + arow) : 0)][akq];

    const int bk  = tid >> 5;
    const int bn4 = (tid & 31) * 4;
    const float* bptr = w2 + (size_t)e * FFN_ * DM + (size_t)bk * DM + n0 + bn4;

    const int tm = (tid >> 4) * 8;
    const int tn = (tid & 15) * 8;

    float acc[8][8];
    #pragma unroll
    for (int i = 0; i < 8; i++)
        #pragma unroll
        for (int j = 0; j < 8; j++) acc[i][j] = 0.f;

    for (int k0 = 0; k0 < FFN_; k0 += 8) {
        float4 av = make_float4(0.f, 0.f, 0.f, 0.f);
        if (avalid) av = *(const float4*)(aptr + k0);
        As[akq + 0][arow] = av.x;
        As[akq + 1][arow] = av.y;
        As[akq + 2][arow] = av.z;
        As[akq + 3][arow] = av.w;
        *(float4*)&Bs[bk][bn4] = *(const float4*)(bptr + (size_t)k0 * DM);
        __syncthreads();

        #pragma unroll
        for (int k = 0; k < 8; k++) {
            float4 a0 = *(float4*)&As[k][tm];
            float4 a1 = *(float4*)&As[k][tm + 4];
            float4 b0 = *(float4*)&Bs[k][tn];
            float4 b1v = *(float4*)&Bs[k][tn + 4];
            float ar[8] = {a0.x, a0.y, a0.z, a0.w, a1.x, a1.y, a1.z, a1.w};
            float br[8] = {b0.x, b0.y, b0.z, b0.w, b1v.x, b1v.y, b1v.z, b1v.w};
            #pragma unroll
            for (int i = 0; i < 8; i++)
                #pragma unroll
                for (int j = 0; j < 8; j++) acc[i][j] += ar[i] * br[j];
        }
        __syncthreads();
    }

    #pragma unroll
    for (int i = 0; i < 8; i++) {
        int m = m0 + tm + i;
        if (m < count) {
            int   tok = g_tok[e][m];
            float g   = g_gate[e][m];
            float* orow = out + (size_t)tok * DM + n0 + tn;
            #pragma unroll
            for (int j = 0; j < 8; j++) {
                float y = acc[i][j] + b2[(size_t)e * DM + n0 + tn + j];
                atomicAdd(&orow[j], g * y);
            }
        }
    }
}

// ---------------- launch ----------------
extern "C" void kernel_launch(void* const* d_in, const int* in_sizes, int n_in,
                              void* d_out, int out_size) {
    const float* x  = (const float*)d_in[0];
    const float* gw = (const float*)d_in[1];
    const float* gb = (const float*)d_in[2];
    const float* w1 = (const float*)d_in[3];
    const float* b1 = (const float*)d_in[4];
    const float* w2 = (const float*)d_in[5];
    const float* b2 = (const float*)d_in[6];
    float* out = (float*)d_out;

    const int T = in_sizes[0] / DM;   // 8192

    init_kernel<<<1, 32>>>();
    route_kernel<<<(T + 7) / 8, 256>>>(x, gw, gb, T);
    base_kernel<<<1, 32>>>();
    cudaMemsetAsync(d_out, 0, (size_t)out_size * sizeof(float), 0);

    dim3 g1((T + 127) / 128, FFN_ / 128, NE);
    gemm1_kernel<<<g1, 256>>>(x, w1, b1);

    dim3 g2((T + 127) / 128, DM / 128, NE);
    gemm2_kernel<<<g2, 256>>>(w2, b2, out);
}

// round 3
// speedup vs baseline: 3.8702x; 3.8702x over previous
#include <cuda_runtime.h>
#include <math.h>
#include <stdint.h>

#define DM    1024
#define FFN_  4096
#define NE    8
#define TMAX  8192
#define GROWS (2*TMAX + 128)

// ---------------- device scratch ----------------
__device__ int   g_counts[NE];
__device__ int   g_base[NE];
__device__ int   g_tok[NE][TMAX];
__device__ float g_gate[NE][TMAX];
__device__ float g_Xg[(size_t)GROWS * DM];    // gathered x, tf32-rounded
__device__ float g_H[(size_t)GROWS * FFN_];   // gelu output, tf32-rounded

// ---------------- helpers ----------------
__device__ __forceinline__ uint32_t smem_u32(const void* p) {
    uint32_t a;
    asm("{ .reg .u64 t; cvta.to.shared.u64 t, %1; cvt.u32.u64 %0, t; }" : "=r"(a) : "l"(p));
    return a;
}
__device__ __forceinline__ float rna_tf32(float v) {
    float o; asm("cvt.rna.tf32.f32 %0, %1;" : "=f"(o) : "f"(v)); return o;
}
__device__ __forceinline__ float gelu_exact(float v) {
    return 0.5f * v * (1.f + erff(v * 0.7071067811865476f));
}

#define CP_ASYNC16(dst, src) \
    asm volatile("cp.async.cg.shared.global [%0], [%1], 16;" :: "r"(dst), "l"(src) : "memory")
#define CP_COMMIT()  asm volatile("cp.async.commit_group;" ::: "memory")
#define CP_WAIT1()   asm volatile("cp.async.wait_group 1;" ::: "memory")
#define CP_WAITALL() asm volatile("cp.async.wait_all;" ::: "memory")

#define MMA_TF32(c, a, b) \
    asm volatile("mma.sync.aligned.m16n8k8.row.col.f32.tf32.tf32.f32 " \
        "{%0,%1,%2,%3}, {%4,%5,%6,%7}, {%8,%9}, {%0,%1,%2,%3};" \
        : "+f"((c)[0]), "+f"((c)[1]), "+f"((c)[2]), "+f"((c)[3]) \
        : "r"((a)[0]), "r"((a)[1]), "r"((a)[2]), "r"((a)[3]), "r"((b)[0]), "r"((b)[1]))

// ---------------- routing ----------------
__global__ void init_kernel() { if (threadIdx.x < NE) g_counts[threadIdx.x] = 0; }

__global__ void base_kernel() {
    if (threadIdx.x == 0) {
        int s = 0;
        #pragma unroll
        for (int e = 0; e < NE; e++) { g_base[e] = s; s += g_counts[e]; }
    }
}

__global__ void route_kernel(const float* __restrict__ x,
                             const float* __restrict__ gw,
                             const float* __restrict__ gb, int T) {
    int warp = (blockIdx.x * blockDim.x + threadIdx.x) >> 5;
    int lane = threadIdx.x & 31;
    if (warp >= T) return;
    const float* xr = x + (size_t)warp * DM;
    float acc[NE];
    #pragma unroll
    for (int e = 0; e < NE; e++) acc[e] = 0.f;
    for (int d = lane; d < DM; d += 32) {
        float xv = xr[d];
        const float4* g4 = (const float4*)(gw + (size_t)d * NE);
        float4 a = g4[0], b = g4[1];
        acc[0] += xv*a.x; acc[1] += xv*a.y; acc[2] += xv*a.z; acc[3] += xv*a.w;
        acc[4] += xv*b.x; acc[5] += xv*b.y; acc[6] += xv*b.z; acc[7] += xv*b.w;
    }
    #pragma unroll
    for (int e = 0; e < NE; e++)
        #pragma unroll
        for (int o = 16; o > 0; o >>= 1) acc[e] += __shfl_xor_sync(0xFFFFFFFFu, acc[e], o);
    if (lane == 0) {
        float v[NE];
        #pragma unroll
        for (int e = 0; e < NE; e++) v[e] = acc[e] + gb[e];
        int i1 = 0;
        #pragma unroll
        for (int e = 1; e < NE; e++) if (v[e] > v[i1]) i1 = e;
        int i2 = (i1 == 0) ? 1 : 0;
        #pragma unroll
        for (int e = 0; e < NE; e++) if (e != i1 && v[e] > v[i2]) i2 = e;
        float e2 = expf(v[i2] - v[i1]);
        float s = 1.f + e2;
        int s1 = atomicAdd(&g_counts[i1], 1);
        g_tok[i1][s1] = warp; g_gate[i1][s1] = 1.f / s;
        int s2 = atomicAdd(&g_counts[i2], 1);
        g_tok[i2][s2] = warp; g_gate[i2][s2] = e2 / s;
    }
}

__global__ void gather_kernel(const float* __restrict__ x) {
    int e = blockIdx.y;
    int slot = blockIdx.x * 2 + (threadIdx.x >> 7);
    if (slot >= g_counts[e]) return;
    int tok = g_tok[e][slot];
    int row = g_base[e] + slot;
    int lane = threadIdx.x & 127;
    const float4* s = (const float4*)(x + (size_t)tok * DM);
    float4* d = (float4*)(g_Xg + (size_t)row * DM);
    #pragma unroll
    for (int i = 0; i < 2; i++) {
        float4 v = s[lane + i * 128];
        v.x = rna_tf32(v.x); v.y = rna_tf32(v.y); v.z = rna_tf32(v.z); v.w = rna_tf32(v.w);
        d[lane + i * 128] = v;
    }
}

// ---------------- mma.sync TF32 grouped GEMM ----------------
// CTA: 128x128 tile, 256 threads = 8 warps (2 x 4), warp tile 64x32.
// smem: A [128][36] (m-major), B [32][136] (k-major over n), double buffered.
#define ASTR 36
#define BSTR 136
#define ABUF (128 * ASTR)            // 4608 floats
#define BBUF (32 * BSTR)             // 4352 floats
#define BUFSZ (ABUF + BBUF)          // 8960 floats
#define SMEM_DYN (2 * BUFSZ * 4)     // 71680 bytes

template<int KDIM, int NDIM, bool GELU_OUT>
__global__ void __launch_bounds__(256)
gemm_mma(const float* __restrict__ Bmat, const float* __restrict__ bias,
         float* __restrict__ outp) {
    const int e = blockIdx.z;
    const int count = g_counts[e];
    const int m0 = blockIdx.x * 128;
    if (m0 >= count) return;
    const int base = g_base[e];
    const int n0 = blockIdx.y * 128;

    extern __shared__ float sm[];
    const uint32_t su = smem_u32(sm);

    const int tid = threadIdx.x;
    const int wid = tid >> 5;
    const int lane = tid & 31;
    const int g = lane >> 2;      // 0..7
    const int tg = lane & 3;      // 0..3
    const int wr = wid & 1;       // warp row: 2 x 64
    const int wc = wid >> 1;      // warp col: 4 x 32

    const float* Asrc = (GELU_OUT ? g_Xg : g_H) + (size_t)(base + m0) * KDIM;
    const float* Bsrc = Bmat + (size_t)e * KDIM * NDIM + n0;

    const int ldq = tid & 7;      // float4 index
    const int ldr = tid >> 3;     // 0..31

    float c[4][4][4];
    #pragma unroll
    for (int i = 0; i < 4; i++)
        #pragma unroll
        for (int j = 0; j < 4; j++)
            #pragma unroll
            for (int k = 0; k < 4; k++) c[i][j][k] = 0.f;

    const int KC = KDIM / 32;

    // -------- tile loader (cp.async) --------
    #define LOAD_TILES(kc_, buf_) do { \
        uint32_t sa = su + (uint32_t)((buf_) * BUFSZ) * 4u; \
        uint32_t sb = sa + (uint32_t)ABUF * 4u; \
        _Pragma("unroll") \
        for (int p = 0; p < 4; p++) { \
            int m = ldr + 32 * p; \
            CP_ASYNC16(sa + (uint32_t)(m * ASTR + ldq * 4) * 4u, \
                       Asrc + (size_t)m * KDIM + (kc_) * 32 + ldq * 4); \
        } \
        _Pragma("unroll") \
        for (int p = 0; p < 4; p++) { \
            int nn = (ldq + 8 * p) * 4; \
            CP_ASYNC16(sb + (uint32_t)(ldr * BSTR + nn) * 4u, \
                       Bsrc + (size_t)((kc_) * 32 + ldr) * NDIM + nn); \
        } \
    } while (0)

    LOAD_TILES(0, 0);
    CP_COMMIT();

    for (int kc = 0; kc < KC; kc++) {
        if (kc + 1 < KC) {
            LOAD_TILES(kc + 1, (kc + 1) & 1);
            CP_COMMIT();
            CP_WAIT1();
        } else {
            CP_WAITALL();
        }
        __syncthreads();

        const float* As = sm + (kc & 1) * BUFSZ;
        const float* Bs = As + ABUF;

        #pragma unroll
        for (int ks = 0; ks < 4; ks++) {
            const int k0 = ks * 8;
            uint32_t a[4][4];
            #pragma unroll
            for (int mf = 0; mf < 4; mf++) {
                int row = wr * 64 + mf * 16 + g;
                a[mf][0] = __float_as_uint(As[row * ASTR + k0 + tg]);
                a[mf][1] = __float_as_uint(As[(row + 8) * ASTR + k0 + tg]);
                a[mf][2] = __float_as_uint(As[row * ASTR + k0 + tg + 4]);
                a[mf][3] = __float_as_uint(As[(row + 8) * ASTR + k0 + tg + 4]);
            }
            uint32_t b[4][2];
            #pragma unroll
            for (int nf = 0; nf < 4; nf++) {
                int col = wc * 32 + nf * 8 + g;
                b[nf][0] = __float_as_uint(rna_tf32(Bs[(k0 + tg) * BSTR + col]));
                b[nf][1] = __float_as_uint(rna_tf32(Bs[(k0 + tg + 4) * BSTR + col]));
            }
            #pragma unroll
            for (int mf = 0; mf < 4; mf++)
                #pragma unroll
                for (int nf = 0; nf < 4; nf++)
                    MMA_TF32(c[mf][nf], a[mf], b[nf]);
        }
        __syncthreads();
    }

    // -------- epilogue --------
    #pragma unroll
    for (int mf = 0; mf < 4; mf++) {
        #pragma unroll
        for (int half = 0; half < 2; half++) {
            int rl = wr * 64 + mf * 16 + g + half * 8;
            int m = m0 + rl;
            if (m >= count) continue;
            if (GELU_OUT) {
                float* hrow = g_H + (size_t)(base + m) * FFN_;
                #pragma unroll
                for (int nf = 0; nf < 4; nf++) {
                    int col = n0 + wc * 32 + nf * 8 + 2 * tg;
                    float2 bb = *(const float2*)(bias + (size_t)e * NDIM + col);
                    float2 v;
                    v.x = rna_tf32(gelu_exact(c[mf][nf][half * 2 + 0] + bb.x));
                    v.y = rna_tf32(gelu_exact(c[mf][nf][half * 2 + 1] + bb.y));
                    *(float2*)(hrow + col) = v;
                }
            } else {
                int tok = g_tok[e][m];
                float gt = g_gate[e][m];
                float* orow = outp + (size_t)tok * DM;
                #pragma unroll
                for (int nf = 0; nf < 4; nf++) {
                    int col = n0 + wc * 32 + nf * 8 + 2 * tg;
                    float2 bb = *(const float2*)(bias + (size_t)e * NDIM + col);
                    atomicAdd(orow + col + 0, gt * (c[mf][nf][half * 2 + 0] + bb.x));
                    atomicAdd(orow + col + 1, gt * (c[mf][nf][half * 2 + 1] + bb.y));
                }
            }
        }
    }
}

// ---------------- launch ----------------
extern "C" void kernel_launch(void* const* d_in, const int* in_sizes, int n_in,
                              void* d_out, int out_size) {
    const float* x  = (const float*)d_in[0];
    const float* gw = (const float*)d_in[1];
    const float* gb = (const float*)d_in[2];
    const float* w1 = (const float*)d_in[3];
    const float* b1 = (const float*)d_in[4];
    const float* w2 = (const float*)d_in[5];
    const float* b2 = (const float*)d_in[6];
    float* out = (float*)d_out;
    const int T = in_sizes[0] / DM;

    static int attr_done = 0;
    if (!attr_done) {
        cudaFuncSetAttribute(gemm_mma<DM, FFN_, true>,
                             cudaFuncAttributeMaxDynamicSharedMemorySize, SMEM_DYN);
        cudaFuncSetAttribute(gemm_mma<FFN_, DM, false>,
                             cudaFuncAttributeMaxDynamicSharedMemorySize, SMEM_DYN);
        attr_done = 1;
    }

    init_kernel<<<1, 32>>>();
    route_kernel<<<(T + 7) / 8, 256>>>(x, gw, gb, T);
    base_kernel<<<1, 32>>>();
    gather_kernel<<<dim3((T + 1) / 2, NE), 256>>>(x);
    cudaMemsetAsync(d_out, 0, (size_t)out_size * sizeof(float), 0);

    gemm_mma<DM, FFN_, true><<<dim3(T / 128, FFN_ / 128, NE), 256, SMEM_DYN>>>(w1, b1, nullptr);
    gemm_mma<FFN_, DM, false><<<dim3(T / 128, DM / 128, NE), 256, SMEM_DYN>>>(w2, b2, out);
}

// round 4
// speedup vs baseline: 5.9231x; 1.5304x over previous
#include <cuda_runtime.h>
#include <cuda_fp16.h>
#include <math.h>
#include <stdint.h>

#define DM    1024
#define FFN_  4096
#define NE    8
#define TMAX  8192
#define GROWS (2*TMAX + 128)

// ---------------- device scratch ----------------
__device__ int    g_counts[NE];
__device__ int    g_base[NE];
__device__ int    g_tok[NE][TMAX];
__device__ float  g_gate[NE][TMAX];
__device__ __half g_Xgh[(size_t)GROWS * DM];
__device__ __half g_Hh[(size_t)GROWS * FFN_];
__device__ __half g_w1h[(size_t)NE * DM * FFN_];
__device__ __half g_w2h[(size_t)NE * FFN_ * DM];

// ---------------- helpers ----------------
__device__ __forceinline__ uint32_t smem_u32(const void* p) {
    uint32_t a;
    asm("{ .reg .u64 t; cvta.to.shared.u64 t, %1; cvt.u32.u64 %0, t; }" : "=r"(a) : "l"(p));
    return a;
}
__device__ __forceinline__ float gelu_exact(float v) {
    return 0.5f * v * (1.f + erff(v * 0.7071067811865476f));
}

#define CP_ASYNC16(dst, src) \
    asm volatile("cp.async.cg.shared.global [%0], [%1], 16;" :: "r"(dst), "l"(src) : "memory")
#define CP_COMMIT()  asm volatile("cp.async.commit_group;" ::: "memory")
#define CP_WAIT1()   asm volatile("cp.async.wait_group 1;" ::: "memory")
#define CP_WAITALL() asm volatile("cp.async.wait_all;" ::: "memory")

#define LDMATRIX_X4(r0,r1,r2,r3, addr) \
    asm volatile("ldmatrix.sync.aligned.m8n8.x4.shared.b16 {%0,%1,%2,%3}, [%4];" \
        : "=r"(r0), "=r"(r1), "=r"(r2), "=r"(r3) : "r"(addr))
#define LDMATRIX_X4_T(r0,r1,r2,r3, addr) \
    asm volatile("ldmatrix.sync.aligned.m8n8.x4.trans.shared.b16 {%0,%1,%2,%3}, [%4];" \
        : "=r"(r0), "=r"(r1), "=r"(r2), "=r"(r3) : "r"(addr))

#define MMA_F16(c, a, b0, b1) \
    asm volatile("mma.sync.aligned.m16n8k16.row.col.f32.f16.f16.f32 " \
        "{%0,%1,%2,%3}, {%4,%5,%6,%7}, {%8,%9}, {%0,%1,%2,%3};" \
        : "+f"((c)[0]), "+f"((c)[1]), "+f"((c)[2]), "+f"((c)[3]) \
        : "r"((a)[0]), "r"((a)[1]), "r"((a)[2]), "r"((a)[3]), "r"(b0), "r"(b1))

// ---------------- routing ----------------
__global__ void init_kernel() { if (threadIdx.x < NE) g_counts[threadIdx.x] = 0; }

__global__ void base_kernel() {
    if (threadIdx.x == 0) {
        int s = 0;
        #pragma unroll
        for (int e = 0; e < NE; e++) { g_base[e] = s; s += g_counts[e]; }
    }
}

__global__ void route_kernel(const float* __restrict__ x,
                             const float* __restrict__ gw,
                             const float* __restrict__ gb, int T) {
    int warp = (blockIdx.x * blockDim.x + threadIdx.x) >> 5;
    int lane = threadIdx.x & 31;
    if (warp >= T) return;
    const float* xr = x + (size_t)warp * DM;
    float acc[NE];
    #pragma unroll
    for (int e = 0; e < NE; e++) acc[e] = 0.f;
    for (int d = lane; d < DM; d += 32) {
        float xv = xr[d];
        const float4* g4 = (const float4*)(gw + (size_t)d * NE);
        float4 a = g4[0], b = g4[1];
        acc[0] += xv*a.x; acc[1] += xv*a.y; acc[2] += xv*a.z; acc[3] += xv*a.w;
        acc[4] += xv*b.x; acc[5] += xv*b.y; acc[6] += xv*b.z; acc[7] += xv*b.w;
    }
    #pragma unroll
    for (int e = 0; e < NE; e++)
        #pragma unroll
        for (int o = 16; o > 0; o >>= 1) acc[e] += __shfl_xor_sync(0xFFFFFFFFu, acc[e], o);
    if (lane == 0) {
        float v[NE];
        #pragma unroll
        for (int e = 0; e < NE; e++) v[e] = acc[e] + gb[e];
        int i1 = 0;
        #pragma unroll
        for (int e = 1; e < NE; e++) if (v[e] > v[i1]) i1 = e;
        int i2 = (i1 == 0) ? 1 : 0;
        #pragma unroll
        for (int e = 0; e < NE; e++) if (e != i1 && v[e] > v[i2]) i2 = e;
        float e2 = expf(v[i2] - v[i1]);
        float s = 1.f + e2;
        int s1 = atomicAdd(&g_counts[i1], 1);
        g_tok[i1][s1] = warp; g_gate[i1][s1] = 1.f / s;
        int s2 = atomicAdd(&g_counts[i2], 1);
        g_tok[i2][s2] = warp; g_gate[i2][s2] = e2 / s;
    }
}

__global__ void gather_kernel(const float* __restrict__ x) {
    int e = blockIdx.y;
    int slot = blockIdx.x * 2 + (threadIdx.x >> 7);
    if (slot >= g_counts[e]) return;
    int tok = g_tok[e][slot];
    int row = g_base[e] + slot;
    int lane = threadIdx.x & 127;
    const float4* s = (const float4*)(x + (size_t)tok * DM);
    uint2* d = (uint2*)(g_Xgh + (size_t)row * DM);
    #pragma unroll
    for (int i = 0; i < 2; i++) {
        float4 v = s[lane + i * 128];
        __half2 h0 = __floats2half2_rn(v.x, v.y);
        __half2 h1 = __floats2half2_rn(v.z, v.w);
        uint2 o;
        o.x = *reinterpret_cast<uint32_t*>(&h0);
        o.y = *reinterpret_cast<uint32_t*>(&h1);
        d[lane + i * 128] = o;
    }
}

// fp32 -> fp16 weight conversion
__global__ void conv_half_kernel(const float4* __restrict__ src, uint2* __restrict__ dst, int n4) {
    int i = blockIdx.x * blockDim.x + threadIdx.x;
    if (i >= n4) return;
    float4 v = src[i];
    __half2 h0 = __floats2half2_rn(v.x, v.y);
    __half2 h1 = __floats2half2_rn(v.z, v.w);
    uint2 o;
    o.x = *reinterpret_cast<uint32_t*>(&h0);
    o.y = *reinterpret_cast<uint32_t*>(&h1);
    dst[i] = o;
}

// ---------------- fp16 mma grouped GEMM ----------------
// CTA 128x128, 256 threads = 8 warps (2x4), warp tile 64x32, k-chunk 32.
// smem (halves): A [128][40], B [32][136], double buffered.
#define ASTRH 40
#define BSTRH 136
#define ABUFB (128 * ASTRH * 2)          // 10240 B
#define BBUFB (32 * BSTRH * 2)           // 8704 B
#define BUFB  (ABUFB + BBUFB)            // 18944 B
#define SMEM_DYN (2 * BUFB)              // 37888 B

template<int KDIM, int NDIM, bool GELU_OUT>
__global__ void __launch_bounds__(256, 2)
gemm_mma(const __half* __restrict__ Bmat, const float* __restrict__ bias,
         float* __restrict__ outp) {
    const int e = blockIdx.z;
    const int count = g_counts[e];
    const int m0 = blockIdx.x * 128;
    if (m0 >= count) return;
    const int base = g_base[e];
    const int n0 = blockIdx.y * 128;

    extern __shared__ char smraw[];
    const uint32_t su = smem_u32(smraw);

    const int tid  = threadIdx.x;
    const int wid  = tid >> 5;
    const int lane = tid & 31;
    const int g    = lane >> 2;
    const int tg   = lane & 3;
    const int wr   = wid & 1;   // 2 warp rows x 64
    const int wc   = wid >> 1;  // 4 warp cols x 32

    const __half* Asrc = (GELU_OUT ? g_Xgh : g_Hh) + (size_t)(base + m0) * KDIM;
    const __half* Bsrc = Bmat + (size_t)e * KDIM * NDIM + n0;

    // cp.async thread mapping
    const int am = tid >> 1;                 // A row 0..127
    const int ac = (tid & 1) * 2;            // A chunk base (16B units), 2 chunks
    const int bk = tid >> 3;                 // B row 0..31
    const int bc = (tid & 7) * 2;            // B chunk base, 2 chunks

    // ldmatrix lane addressing
    const int lane_r  = (lane & 7) + ((lane >> 3) & 1) * 8;  // 0..15
    const int lane_k8 = (lane >> 4) * 16;                    // byte offset 0/16

    float c[4][4][4];
    #pragma unroll
    for (int i = 0; i < 4; i++)
        #pragma unroll
        for (int j = 0; j < 4; j++)
            #pragma unroll
            for (int k = 0; k < 4; k++) c[i][j][k] = 0.f;

    const int KC = KDIM / 32;

    #define LOAD_TILES(kc_, buf_) do { \
        uint32_t sa = su + (buf_) * BUFB; \
        uint32_t sb = sa + ABUFB; \
        const __half* asp = Asrc + (size_t)am * KDIM + (kc_) * 32; \
        _Pragma("unroll") \
        for (int j = 0; j < 2; j++) \
            CP_ASYNC16(sa + (uint32_t)(am * 80 + (ac + j) * 16), asp + (ac + j) * 8); \
        const __half* bsp = Bsrc + (size_t)((kc_) * 32 + bk) * NDIM; \
        _Pragma("unroll") \
        for (int j = 0; j < 2; j++) \
            CP_ASYNC16(sb + (uint32_t)(bk * 272 + (bc + j) * 16), bsp + (bc + j) * 8); \
    } while (0)

    LOAD_TILES(0, 0);
    CP_COMMIT();

    for (int kc = 0; kc < KC; kc++) {
        if (kc + 1 < KC) {
            LOAD_TILES(kc + 1, (kc + 1) & 1);
            CP_COMMIT();
            CP_WAIT1();
        } else {
            CP_WAITALL();
        }
        __syncthreads();

        const uint32_t sa = su + (kc & 1) * BUFB;
        const uint32_t sb = sa + ABUFB;
        const uint32_t a_base = sa + (uint32_t)((wr * 64 + lane_r) * 80) + lane_k8;
        const uint32_t b_base = sb + (uint32_t)(lane_r * 272 + wc * 64) + lane_k8;

        #pragma unroll
        for (int ks = 0; ks < 2; ks++) {
            uint32_t a[4][4];
            #pragma unroll
            for (int mf = 0; mf < 4; mf++)
                LDMATRIX_X4(a[mf][0], a[mf][1], a[mf][2], a[mf][3],
                            a_base + mf * 1280 + ks * 32);
            uint32_t b[4][2];
            #pragma unroll
            for (int np = 0; np < 2; np++) {
                uint32_t r0, r1, r2, r3;
                LDMATRIX_X4_T(r0, r1, r2, r3, b_base + ks * 4352 + np * 32);
                b[np * 2 + 0][0] = r0; b[np * 2 + 0][1] = r1;
                b[np * 2 + 1][0] = r2; b[np * 2 + 1][1] = r3;
            }
            #pragma unroll
            for (int mf = 0; mf < 4; mf++)
                #pragma unroll
                for (int nf = 0; nf < 4; nf++)
                    MMA_F16(c[mf][nf], a[mf], b[nf][0], b[nf][1]);
        }
        __syncthreads();
    }

    // -------- epilogue --------
    #pragma unroll
    for (int mf = 0; mf < 4; mf++) {
        #pragma unroll
        for (int half_ = 0; half_ < 2; half_++) {
            int rl = wr * 64 + mf * 16 + g + half_ * 8;
            int m = m0 + rl;
            if (m >= count) continue;
            if (GELU_OUT) {
                __half* hrow = g_Hh + (size_t)(base + m) * FFN_;
                #pragma unroll
                for (int nf = 0; nf < 4; nf++) {
                    int col = n0 + wc * 32 + nf * 8 + 2 * tg;
                    float2 bb = *(const float2*)(bias + (size_t)e * NDIM + col);
                    __half2 hv = __floats2half2_rn(
                        gelu_exact(c[mf][nf][half_ * 2 + 0] + bb.x),
                        gelu_exact(c[mf][nf][half_ * 2 + 1] + bb.y));
                    *reinterpret_cast<__half2*>(hrow + col) = hv;
                }
            } else {
                int tok = g_tok[e][m];
                float gt = g_gate[e][m];
                float* orow = outp + (size_t)tok * DM;
                #pragma unroll
                for (int nf = 0; nf < 4; nf++) {
                    int col = n0 + wc * 32 + nf * 8 + 2 * tg;
                    float2 bb = *(const float2*)(bias + (size_t)e * NDIM + col);
                    atomicAdd(orow + col + 0, gt * (c[mf][nf][half_ * 2 + 0] + bb.x));
                    atomicAdd(orow + col + 1, gt * (c[mf][nf][half_ * 2 + 1] + bb.y));
                }
            }
        }
    }
}

// ---------------- launch ----------------
extern "C" void kernel_launch(void* const* d_in, const int* in_sizes, int n_in,
                              void* d_out, int out_size) {
    const float* x  = (const float*)d_in[0];
    const float* gw = (const float*)d_in[1];
    const float* gb = (const float*)d_in[2];
    const float* w1 = (const float*)d_in[3];
    const float* b1 = (const float*)d_in[4];
    const float* w2 = (const float*)d_in[5];
    const float* b2 = (const float*)d_in[6];
    float* out = (float*)d_out;
    const int T = in_sizes[0] / DM;

    __half* w1h; cudaGetSymbolAddress((void**)&w1h, g_w1h);
    __half* w2h; cudaGetSymbolAddress((void**)&w2h, g_w2h);

    init_kernel<<<1, 32>>>();
    route_kernel<<<(T + 7) / 8, 256>>>(x, gw, gb, T);
    base_kernel<<<1, 32>>>();
    gather_kernel<<<dim3((T + 1) / 2, NE), 256>>>(x);

    const int n4 = NE * DM * FFN_ / 4;
    conv_half_kernel<<<(n4 + 255) / 256, 256>>>((const float4*)w1, (uint2*)w1h, n4);
    conv_half_kernel<<<(n4 + 255) / 256, 256>>>((const float4*)w2, (uint2*)w2h, n4);

    cudaMemsetAsync(d_out, 0, (size_t)out_size * sizeof(float), 0);

    gemm_mma<DM, FFN_, true><<<dim3(T / 128, FFN_ / 128, NE), 256, SMEM_DYN>>>(w1h, b1, nullptr);
    gemm_mma<FFN_, DM, false><<<dim3(T / 128, DM / 128, NE), 256, SMEM_DYN>>>(w2h, b2, out);
}

// round 5
// speedup vs baseline: 6.6056x; 1.1152x over previous
#include <cuda_runtime.h>
#include <cuda_fp16.h>
#include <math.h>
#include <stdint.h>

#define DM    1024
#define FFN_  4096
#define NE    8
#define TMAX  8192
#define GROWS (2*TMAX + 128)

// ---------------- device scratch ----------------
__device__ int    g_counts[NE];
__device__ int    g_base[NE];
__device__ int    g_tok[NE][TMAX];
__device__ float  g_gate[NE][TMAX];
__device__ __half g_Xgh[(size_t)GROWS * DM];
__device__ __half g_Hh[(size_t)GROWS * FFN_];
__device__ __half g_w1h[(size_t)NE * DM * FFN_];
__device__ __half g_w2h[(size_t)NE * FFN_ * DM];

// ---------------- helpers ----------------
__device__ __forceinline__ uint32_t smem_u32(const void* p) {
    uint32_t a;
    asm("{ .reg .u64 t; cvta.to.shared.u64 t, %1; cvt.u32.u64 %0, t; }" : "=r"(a) : "l"(p));
    return a;
}
__device__ __forceinline__ float gelu_exact(float v) {
    return 0.5f * v * (1.f + erff(v * 0.7071067811865476f));
}

#define CP_ASYNC16(dst, src) \
    asm volatile("cp.async.cg.shared.global [%0], [%1], 16;" :: "r"(dst), "l"(src) : "memory")
#define CP_COMMIT()  asm volatile("cp.async.commit_group;" ::: "memory")
#define CP_WAIT2()   asm volatile("cp.async.wait_group 2;" ::: "memory")

#define LDMATRIX_X4(r0,r1,r2,r3, addr) \
    asm volatile("ldmatrix.sync.aligned.m8n8.x4.shared.b16 {%0,%1,%2,%3}, [%4];" \
        : "=r"(r0), "=r"(r1), "=r"(r2), "=r"(r3) : "r"(addr))
#define LDMATRIX_X4_T(r0,r1,r2,r3, addr) \
    asm volatile("ldmatrix.sync.aligned.m8n8.x4.trans.shared.b16 {%0,%1,%2,%3}, [%4];" \
        : "=r"(r0), "=r"(r1), "=r"(r2), "=r"(r3) : "r"(addr))

#define MMA_F16(c, a, b0, b1) \
    asm volatile("mma.sync.aligned.m16n8k16.row.col.f32.f16.f16.f32 " \
        "{%0,%1,%2,%3}, {%4,%5,%6,%7}, {%8,%9}, {%0,%1,%2,%3};" \
        : "+f"((c)[0]), "+f"((c)[1]), "+f"((c)[2]), "+f"((c)[3]) \
        : "r"((a)[0]), "r"((a)[1]), "r"((a)[2]), "r"((a)[3]), "r"(b0), "r"(b1))

// ---------------- routing ----------------
__global__ void init_kernel() { if (threadIdx.x < NE) g_counts[threadIdx.x] = 0; }

__global__ void base_kernel() {
    if (threadIdx.x == 0) {
        int s = 0;
        #pragma unroll
        for (int e = 0; e < NE; e++) { g_base[e] = s; s += g_counts[e]; }
    }
}

__global__ void route_kernel(const float* __restrict__ x,
                             const float* __restrict__ gw,
                             const float* __restrict__ gb, int T) {
    int warp = (blockIdx.x * blockDim.x + threadIdx.x) >> 5;
    int lane = threadIdx.x & 31;
    if (warp >= T) return;
    const float* xr = x + (size_t)warp * DM;
    float acc[NE];
    #pragma unroll
    for (int e = 0; e < NE; e++) acc[e] = 0.f;
    for (int d = lane; d < DM; d += 32) {
        float xv = xr[d];
        const float4* g4 = (const float4*)(gw + (size_t)d * NE);
        float4 a = g4[0], b = g4[1];
        acc[0] += xv*a.x; acc[1] += xv*a.y; acc[2] += xv*a.z; acc[3] += xv*a.w;
        acc[4] += xv*b.x; acc[5] += xv*b.y; acc[6] += xv*b.z; acc[7] += xv*b.w;
    }
    #pragma unroll
    for (int e = 0; e < NE; e++)
        #pragma unroll
        for (int o = 16; o > 0; o >>= 1) acc[e] += __shfl_xor_sync(0xFFFFFFFFu, acc[e], o);
    if (lane == 0) {
        float v[NE];
        #pragma unroll
        for (int e = 0; e < NE; e++) v[e] = acc[e] + gb[e];
        int i1 = 0;
        #pragma unroll
        for (int e = 1; e < NE; e++) if (v[e] > v[i1]) i1 = e;
        int i2 = (i1 == 0) ? 1 : 0;
        #pragma unroll
        for (int e = 0; e < NE; e++) if (e != i1 && v[e] > v[i2]) i2 = e;
        float e2 = expf(v[i2] - v[i1]);
        float s = 1.f + e2;
        int s1 = atomicAdd(&g_counts[i1], 1);
        g_tok[i1][s1] = warp; g_gate[i1][s1] = 1.f / s;
        int s2 = atomicAdd(&g_counts[i2], 1);
        g_tok[i2][s2] = warp; g_gate[i2][s2] = e2 / s;
    }
}

__global__ void gather_kernel(const float* __restrict__ x) {
    int e = blockIdx.y;
    int slot = blockIdx.x * 2 + (threadIdx.x >> 7);
    if (slot >= g_counts[e]) return;
    int tok = g_tok[e][slot];
    int row = g_base[e] + slot;
    int lane = threadIdx.x & 127;
    const float4* s = (const float4*)(x + (size_t)tok * DM);
    uint2* d = (uint2*)(g_Xgh + (size_t)row * DM);
    #pragma unroll
    for (int i = 0; i < 2; i++) {
        float4 v = s[lane + i * 128];
        __half2 h0 = __floats2half2_rn(v.x, v.y);
        __half2 h1 = __floats2half2_rn(v.z, v.w);
        uint2 o;
        o.x = *reinterpret_cast<uint32_t*>(&h0);
        o.y = *reinterpret_cast<uint32_t*>(&h1);
        d[lane + i * 128] = o;
    }
}

// fp32 -> fp16 weight conversion (8 floats / thread, 16B store)
__global__ void conv_half_kernel(const float4* __restrict__ src, uint4* __restrict__ dst, int n8) {
    int i = blockIdx.x * blockDim.x + threadIdx.x;
    if (i >= n8) return;
    float4 v0 = src[i * 2], v1 = src[i * 2 + 1];
    __half2 h0 = __floats2half2_rn(v0.x, v0.y);
    __half2 h1 = __floats2half2_rn(v0.z, v0.w);
    __half2 h2 = __floats2half2_rn(v1.x, v1.y);
    __half2 h3 = __floats2half2_rn(v1.z, v1.w);
    uint4 o;
    o.x = *reinterpret_cast<uint32_t*>(&h0);
    o.y = *reinterpret_cast<uint32_t*>(&h1);
    o.z = *reinterpret_cast<uint32_t*>(&h2);
    o.w = *reinterpret_cast<uint32_t*>(&h3);
    dst[i] = o;
}

// ---------------- fp16 mma grouped GEMM ----------------
// CTA 128x128, 256 threads = 8 warps (2x4), warp tile 64x32, k-chunk 32.
// smem (halves): A [128][40], B [32][136], 4-stage pipeline.
#define ASTRH 40
#define BSTRH 136
#define ABUFB (128 * ASTRH * 2)          // 10240 B
#define BBUFB (32 * BSTRH * 2)           // 8704 B
#define BUFB  (ABUFB + BBUFB)            // 18944 B
#define NSTAGE 4
#define SMEM_DYN (NSTAGE * BUFB)         // 75776 B

template<int KDIM, int NDIM, bool GELU_OUT>
__global__ void __launch_bounds__(256, 2)
gemm_mma(const __half* __restrict__ Bmat, const float* __restrict__ bias,
         float* __restrict__ outp) {
    const int e = blockIdx.z;
    const int count = g_counts[e];
    const int m0 = blockIdx.x * 128;
    if (m0 >= count) return;
    const int base = g_base[e];
    const int n0 = blockIdx.y * 128;

    extern __shared__ char smraw[];
    const uint32_t su = smem_u32(smraw);

    const int tid  = threadIdx.x;
    const int wid  = tid >> 5;
    const int lane = tid & 31;
    const int g    = lane >> 2;
    const int tg   = lane & 3;
    const int wr   = wid & 1;   // 2 warp rows x 64
    const int wc   = wid >> 1;  // 4 warp cols x 32

    const __half* Asrc = (GELU_OUT ? g_Xgh : g_Hh) + (size_t)(base + m0) * KDIM;
    const __half* Bsrc = Bmat + (size_t)e * KDIM * NDIM + n0;

    const int am = tid >> 1;
    const int ac = (tid & 1) * 2;
    const int bk = tid >> 3;
    const int bc = (tid & 7) * 2;

    const int lane_r  = (lane & 7) + ((lane >> 3) & 1) * 8;
    const int lane_k8 = (lane >> 4) * 16;

    float c[4][4][4];
    #pragma unroll
    for (int i = 0; i < 4; i++)
        #pragma unroll
        for (int j = 0; j < 4; j++)
            #pragma unroll
            for (int k = 0; k < 4; k++) c[i][j][k] = 0.f;

    const int KC = KDIM / 32;

    #define LOAD_TILES(kc_, buf_) do { \
        uint32_t sa = su + (buf_) * BUFB; \
        uint32_t sb = sa + ABUFB; \
        const __half* asp = Asrc + (size_t)am * KDIM + (kc_) * 32; \
        _Pragma("unroll") \
        for (int j = 0; j < 2; j++) \
            CP_ASYNC16(sa + (uint32_t)(am * 80 + (ac + j) * 16), asp + (ac + j) * 8); \
        const __half* bsp = Bsrc + (size_t)((kc_) * 32 + bk) * NDIM; \
        _Pragma("unroll") \
        for (int j = 0; j < 2; j++) \
            CP_ASYNC16(sb + (uint32_t)(bk * 272 + (bc + j) * 16), bsp + (bc + j) * 8); \
    } while (0)

    // prologue: fill 3 of 4 stages
    LOAD_TILES(0, 0); CP_COMMIT();
    LOAD_TILES(1, 1); CP_COMMIT();
    LOAD_TILES(2, 2); CP_COMMIT();

    for (int kc = 0; kc < KC; kc++) {
        CP_WAIT2();          // stage kc complete
        __syncthreads();     // all warps done reading stage kc-1 (reuse target)
        if (kc + 3 < KC) LOAD_TILES(kc + 3, (kc + 3) & 3);
        CP_COMMIT();         // always commit (possibly empty) to keep group count

        const uint32_t sa = su + (kc & 3) * BUFB;
        const uint32_t sb = sa + ABUFB;
        const uint32_t a_base = sa + (uint32_t)((wr * 64 + lane_r) * 80) + lane_k8;
        const uint32_t b_base = sb + (uint32_t)(lane_r * 272 + wc * 64) + lane_k8;

        #pragma unroll
        for (int ks = 0; ks < 2; ks++) {
            uint32_t a[4][4];
            #pragma unroll
            for (int mf = 0; mf < 4; mf++)
                LDMATRIX_X4(a[mf][0], a[mf][1], a[mf][2], a[mf][3],
                            a_base + mf * 1280 + ks * 32);
            uint32_t b[4][2];
            #pragma unroll
            for (int np = 0; np < 2; np++) {
                uint32_t r0, r1, r2, r3;
                LDMATRIX_X4_T(r0, r1, r2, r3, b_base + ks * 4352 + np * 32);
                b[np * 2 + 0][0] = r0; b[np * 2 + 0][1] = r1;
                b[np * 2 + 1][0] = r2; b[np * 2 + 1][1] = r3;
            }
            #pragma unroll
            for (int mf = 0; mf < 4; mf++)
                #pragma unroll
                for (int nf = 0; nf < 4; nf++)
                    MMA_F16(c[mf][nf], a[mf], b[nf][0], b[nf][1]);
        }
    }

    // -------- epilogue --------
    #pragma unroll
    for (int mf = 0; mf < 4; mf++) {
        #pragma unroll
        for (int half_ = 0; half_ < 2; half_++) {
            int rl = wr * 64 + mf * 16 + g + half_ * 8;
            int m = m0 + rl;
            if (m >= count) continue;
            if (GELU_OUT) {
                __half* hrow = g_Hh + (size_t)(base + m) * FFN_;
                #pragma unroll
                for (int nf = 0; nf < 4; nf++) {
                    int col = n0 + wc * 32 + nf * 8 + 2 * tg;
                    float2 bb = *(const float2*)(bias + (size_t)e * NDIM + col);
                    __half2 hv = __floats2half2_rn(
                        gelu_exact(c[mf][nf][half_ * 2 + 0] + bb.x),
                        gelu_exact(c[mf][nf][half_ * 2 + 1] + bb.y));
                    *reinterpret_cast<__half2*>(hrow + col) = hv;
                }
            } else {
                int tok = g_tok[e][m];
                float gt = g_gate[e][m];
                float* orow = outp + (size_t)tok * DM;
                #pragma unroll
                for (int nf = 0; nf < 4; nf++) {
                    int col = n0 + wc * 32 + nf * 8 + 2 * tg;
                    float2 bb = *(const float2*)(bias + (size_t)e * NDIM + col);
                    atomicAdd(orow + col + 0, gt * (c[mf][nf][half_ * 2 + 0] + bb.x));
                    atomicAdd(orow + col + 1, gt * (c[mf][nf][half_ * 2 + 1] + bb.y));
                }
            }
        }
    }
}

// ---------------- launch ----------------
extern "C" void kernel_launch(void* const* d_in, const int* in_sizes, int n_in,
                              void* d_out, int out_size) {
    const float* x  = (const float*)d_in[0];
    const float* gw = (const float*)d_in[1];
    const float* gb = (const float*)d_in[2];
    const float* w1 = (const float*)d_in[3];
    const float* b1 = (const float*)d_in[4];
    const float* w2 = (const float*)d_in[5];
    const float* b2 = (const float*)d_in[6];
    float* out = (float*)d_out;
    const int T = in_sizes[0] / DM;

    __half* w1h; cudaGetSymbolAddress((void**)&w1h, g_w1h);
    __half* w2h; cudaGetSymbolAddress((void**)&w2h, g_w2h);

    static int attr_done = 0;
    if (!attr_done) {
        cudaFuncSetAttribute(gemm_mma<DM, FFN_, true>,
                             cudaFuncAttributeMaxDynamicSharedMemorySize, SMEM_DYN);
        cudaFuncSetAttribute(gemm_mma<FFN_, DM, false>,
                             cudaFuncAttributeMaxDynamicSharedMemorySize, SMEM_DYN);
        attr_done = 1;
    }

    init_kernel<<<1, 32>>>();
    route_kernel<<<(T + 7) / 8, 256>>>(x, gw, gb, T);
    base_kernel<<<1, 32>>>();
    gather_kernel<<<dim3((T + 1) / 2, NE), 256>>>(x);

    const int n8 = NE * DM * FFN_ / 8;
    conv_half_kernel<<<(n8 + 255) / 256, 256>>>((const float4*)w1, (uint4*)w1h, n8);
    conv_half_kernel<<<(n8 + 255) / 256, 256>>>((const float4*)w2, (uint4*)w2h, n8);

    cudaMemsetAsync(d_out, 0, (size_t)out_size * sizeof(float), 0);

    gemm_mma<DM, FFN_, true><<<dim3(T / 128, FFN_ / 128, NE), 256, SMEM_DYN>>>(w1h, b1, nullptr);
    gemm_mma<FFN_, DM, false><<<dim3(T / 128, DM / 128, NE), 256, SMEM_DYN>>>(w2h, b2, out);
}